// round 15
// baseline (speedup 1.0000x reference)
#include <cuda_runtime.h>
#include <cuda_bf16.h>
#include <cstdint>
#include <math.h>

#define D_MODEL 1024
#define NHEAD 16
#define DKH 64
#define BATCH 4
#define SEQ 2048
#define MTOK (BATCH * SEQ)   // 8192

// 0.125 * log2(e): folded into Q so attention scores are exp2-ready
#define QSCALE 0.18033688011112042f

// ---------------------------------------------------------------------------
// Scratch (alloc-free rule: __device__ globals)
// ---------------------------------------------------------------------------
__device__ __nv_bfloat16 g_xh[MTOK * D_MODEL];
__device__ __nv_bfloat16 g_xl[MTOK * D_MODEL];
__device__ __nv_bfloat16 g_qh[MTOK * D_MODEL];   // [B,H,S,64] (pre-scaled)
__device__ __nv_bfloat16 g_ql[MTOK * D_MODEL];
__device__ __nv_bfloat16 g_kh[MTOK * D_MODEL];
__device__ __nv_bfloat16 g_kl[MTOK * D_MODEL];
__device__ __nv_bfloat16 g_vh[MTOK * D_MODEL];
__device__ __nv_bfloat16 g_vl[MTOK * D_MODEL];
__device__ __nv_bfloat16 g_ah[MTOK * D_MODEL];   // attn out [B,S,D]
__device__ __nv_bfloat16 g_al[MTOK * D_MODEL];
__device__ __nv_bfloat16 g_wqh[D_MODEL * D_MODEL];
__device__ __nv_bfloat16 g_wql[D_MODEL * D_MODEL];
__device__ __nv_bfloat16 g_wkh[D_MODEL * D_MODEL];
__device__ __nv_bfloat16 g_wkl[D_MODEL * D_MODEL];
__device__ __nv_bfloat16 g_wvh[D_MODEL * D_MODEL];
__device__ __nv_bfloat16 g_wvl[D_MODEL * D_MODEL];
__device__ __nv_bfloat16 g_woh[D_MODEL * D_MODEL];
__device__ __nv_bfloat16 g_wol[D_MODEL * D_MODEL];

// ---------------------------------------------------------------------------
// helpers (arch-portable only: cp.async / ldmatrix / mma.sync)
// ---------------------------------------------------------------------------
__device__ __forceinline__ uint32_t smem_u32(const void* p) {
    uint32_t a;
    asm("{ .reg .u64 t; cvta.to.shared.u64 t, %1; cvt.u32.u64 %0, t; }"
        : "=r"(a) : "l"(p));
    return a;
}

#define LDMATRIX_X4(r0, r1, r2, r3, addr) \
    asm volatile("ldmatrix.sync.aligned.m8n8.x4.shared.b16 {%0,%1,%2,%3}, [%4];" \
        : "=r"(r0), "=r"(r1), "=r"(r2), "=r"(r3) : "r"(addr))

#define LDMATRIX_X4_T(r0, r1, r2, r3, addr) \
    asm volatile("ldmatrix.sync.aligned.m8n8.x4.trans.shared.b16 {%0,%1,%2,%3}, [%4];" \
        : "=r"(r0), "=r"(r1), "=r"(r2), "=r"(r3) : "r"(addr))

#define MMA16816(d, a0, a1, a2, a3, b0, b1) \
    asm volatile("mma.sync.aligned.m16n8k16.row.col.f32.bf16.bf16.f32 " \
        "{%0,%1,%2,%3}, {%4,%5,%6,%7}, {%8,%9}, {%0,%1,%2,%3};" \
        : "+f"((d)[0]), "+f"((d)[1]), "+f"((d)[2]), "+f"((d)[3]) \
        : "r"(a0), "r"(a1), "r"(a2), "r"(a3), "r"(b0), "r"(b1))

#define CP_ASYNC16(saddr, gaddr) \
    asm volatile("cp.async.cg.shared.global [%0], [%1], 16;" \
        :: "r"(saddr), "l"(gaddr))
#define CP_COMMIT() asm volatile("cp.async.commit_group;" ::: "memory")
#define CP_WAIT(n)  asm volatile("cp.async.wait_group %0;" :: "n"(n) : "memory")

#define PACK_BF16X2(r, lo, hi) \
    asm("cvt.rn.bf16x2.f32 %0, %1, %2;" : "=r"(r) : "f"(hi), "f"(lo))

__device__ __forceinline__ void split2(float v0, float v1,
                                       uint32_t& ph, uint32_t& pl) {
    PACK_BF16X2(ph, v0, v1);
    const float f0 = __uint_as_float(ph << 16);
    const float f1 = __uint_as_float(ph & 0xffff0000u);
    PACK_BF16X2(pl, v0 - f0, v1 - f1);
}

__device__ __forceinline__ float ex2(float x) {
    float y;
    asm("ex2.approx.f32 %0, %1;" : "=f"(y) : "f"(x));
    return y;
}

// ---------------------------------------------------------------------------
// fp32 -> bf16 hi/lo splits
// ---------------------------------------------------------------------------
__global__ void __launch_bounds__(256) split_kernel(
    const float* __restrict__ in,
    __nv_bfloat16* __restrict__ hi, __nv_bfloat16* __restrict__ lo, int n4)
{
    int i = blockIdx.x * 256 + threadIdx.x;
    if (i >= n4) return;
    float4 v = ((const float4*)in)[i];
    uint32_t h01, l01, h23, l23;
    split2(v.x, v.y, h01, l01);
    split2(v.z, v.w, h23, l23);
    ((uint32_t*)hi)[2 * i]     = h01;
    ((uint32_t*)hi)[2 * i + 1] = h23;
    ((uint32_t*)lo)[2 * i]     = l01;
    ((uint32_t*)lo)[2 * i + 1] = l23;
}

#define NW4 (D_MODEL * D_MODEL / 4)

__global__ void __launch_bounds__(256) split4_kernel(
    const float* __restrict__ w0, const float* __restrict__ w1,
    const float* __restrict__ w2, const float* __restrict__ w3,
    __nv_bfloat16* __restrict__ h0, __nv_bfloat16* __restrict__ l0,
    __nv_bfloat16* __restrict__ h1, __nv_bfloat16* __restrict__ l1,
    __nv_bfloat16* __restrict__ h2, __nv_bfloat16* __restrict__ l2,
    __nv_bfloat16* __restrict__ h3, __nv_bfloat16* __restrict__ l3)
{
    int id = blockIdx.x * 256 + threadIdx.x;
    const int which = id / NW4;
    const int i = id - which * NW4;
    const float* in = (which == 0) ? w0 : (which == 1) ? w1
                      : (which == 2) ? w2 : w3;
    __nv_bfloat16* hi = (which == 0) ? h0 : (which == 1) ? h1
                        : (which == 2) ? h2 : h3;
    __nv_bfloat16* lo = (which == 0) ? l0 : (which == 1) ? l1
                        : (which == 2) ? l2 : l3;
    float4 v = ((const float4*)in)[i];
    uint32_t h01, l01, h23, l23;
    split2(v.x, v.y, h01, l01);
    split2(v.z, v.w, h23, l23);
    ((uint32_t*)hi)[2 * i]     = h01;
    ((uint32_t*)hi)[2 * i + 1] = h23;
    ((uint32_t*)lo)[2 * i]     = l01;
    ((uint32_t*)lo)[2 * i + 1] = l23;
}

// ---------------------------------------------------------------------------
// mma.sync bf16 3-pass GEMM: C[m,n] = sum_k A[m,k]*B[n,k]
// NEW: 256x128 tile/CTA, 8 warps of 64x64, BK=32, XOR swizzle, 3-stage,
// 1 CTA/SM. Improves MMA/LDSM ratio 4->6 and LDGSTS/output 25% — relieves
// the MIO issue port which was the binding resource.
// ---------------------------------------------------------------------------
#define BM 256
#define BN 128
#define BK 32
#define CHUNKS (D_MODEL / BK)          // 32
#define A_TILE_B (256 * 64)            // 16384
#define B_TILE_B (128 * 64)            // 8192
#define STAGE_B (2 * A_TILE_B + 2 * B_TILE_B)   // 49152
#define GEMM_SMEM (3 * STAGE_B)        // 147456

template <int MODE>
__device__ __forceinline__ void gemm_body(
    const __nv_bfloat16* __restrict__ Ah, const __nv_bfloat16* __restrict__ Al,
    const __nv_bfloat16* __restrict__ Bh, const __nv_bfloat16* __restrict__ Bl,
    __nv_bfloat16* __restrict__ Ch, __nv_bfloat16* __restrict__ Cl,
    float* __restrict__ Cf, const int bm, const int bn, const float cscale)
{
    extern __shared__ __align__(128) char smem[];
    const uint32_t sbase = smem_u32(smem);
    const int tid  = threadIdx.x;
    const int wid  = tid >> 5;
    const int lane = tid & 31;
    const int K = D_MODEL;

    const int warp_m = wid >> 1;   // 0..3 (64 rows each)
    const int warp_n = wid & 1;    // 0..1 (64 cols each)

    auto load_stage = [&](int chunk, int s) {
        const uint32_t st = sbase + s * STAGE_B;
        const int k0 = chunk * BK;
#pragma unroll
        for (int u = 0; u < 12; u++) {
            const int id = u * 256 + tid;      // 0..3071
            uint32_t soff;
            const __nv_bfloat16* g;
            int grow, c;
            if (u < 8) {                        // A tiles (id < 2048)
                const int t = id >> 10;         // 0:Ah 1:Al
                const int idx = id & 1023;
                const int row = idx >> 2;       // 0..255
                c = idx & 3;
                g = t ? Al : Ah;
                grow = bm + row;
                soff = t * A_TILE_B + row * 64 +
                       (((uint32_t)(c ^ ((row >> 1) & 3))) << 4);
            } else {                            // B tiles
                const int id2 = id - 2048;
                const int t = id2 >> 9;         // 0:Bh 1:Bl
                const int idx = id2 & 511;
                const int row = idx >> 2;       // 0..127
                c = idx & 3;
                g = t ? Bl : Bh;
                grow = bn + row;
                soff = 2 * A_TILE_B + t * B_TILE_B + row * 64 +
                       (((uint32_t)(c ^ ((row >> 1) & 3))) << 4);
            }
            CP_ASYNC16(st + soff, g + (size_t)grow * K + k0 + c * 8);
        }
        CP_COMMIT();
    };

    load_stage(0, 0);
    load_stage(1, 1);
    load_stage(2, 2);

    float acc[4][8][4];
#pragma unroll
    for (int i = 0; i < 4; i++)
#pragma unroll
        for (int j = 0; j < 8; j++)
#pragma unroll
            for (int r = 0; r < 4; r++) acc[i][j][r] = 0.0f;

    const int a_row = warp_m * 64 + (lane & 15);
    const uint32_t a_off = (uint32_t)a_row * 64 +
        ((uint32_t)(((lane >> 4) ^ ((a_row >> 1) & 3))) << 4);
    const int b_row = warp_n * 64 + ((lane >> 4) & 1) * 8 + (lane & 7);
    const uint32_t b_off = (uint32_t)b_row * 64 +
        ((uint32_t)((((lane >> 3) & 1) ^ ((b_row >> 1) & 3))) << 4);

    int s = 0;
    for (int chunk = 0; chunk < CHUNKS; chunk++) {
        if (chunk < CHUNKS - 2)       CP_WAIT(2);
        else if (chunk == CHUNKS - 2) CP_WAIT(1);
        else                          CP_WAIT(0);
        __syncthreads();
        const uint32_t st = sbase + s * STAGE_B;
        const uint32_t aH = st + a_off;
        const uint32_t aL = st + A_TILE_B + a_off;
        const uint32_t bH = st + 2 * A_TILE_B + b_off;
        const uint32_t bL = bH + B_TILE_B;

#pragma unroll
        for (int ks = 0; ks < 2; ks++) {
            const uint32_t kx = (uint32_t)ks << 5;
            uint32_t fAH[4][4], fAL[4][4], fBH[8][2], fBL[8][2];
#pragma unroll
            for (int mt = 0; mt < 4; mt++) {
                LDMATRIX_X4(fAH[mt][0], fAH[mt][1], fAH[mt][2], fAH[mt][3],
                            (aH + mt * 1024) ^ kx);
                LDMATRIX_X4(fAL[mt][0], fAL[mt][1], fAL[mt][2], fAL[mt][3],
                            (aL + mt * 1024) ^ kx);
            }
#pragma unroll
            for (int np = 0; np < 4; np++) {
                LDMATRIX_X4(fBH[2 * np][0], fBH[2 * np][1],
                            fBH[2 * np + 1][0], fBH[2 * np + 1][1],
                            (bH + np * 1024) ^ kx);
                LDMATRIX_X4(fBL[2 * np][0], fBL[2 * np][1],
                            fBL[2 * np + 1][0], fBL[2 * np + 1][1],
                            (bL + np * 1024) ^ kx);
            }
#pragma unroll
            for (int mt = 0; mt < 4; mt++)
#pragma unroll
                for (int nt = 0; nt < 8; nt++) {
                    MMA16816(acc[mt][nt], fAH[mt][0], fAH[mt][1], fAH[mt][2],
                             fAH[mt][3], fBH[nt][0], fBH[nt][1]);
                    MMA16816(acc[mt][nt], fAH[mt][0], fAH[mt][1], fAH[mt][2],
                             fAH[mt][3], fBL[nt][0], fBL[nt][1]);
                    MMA16816(acc[mt][nt], fAL[mt][0], fAL[mt][1], fAL[mt][2],
                             fAL[mt][3], fBH[nt][0], fBH[nt][1]);
                }
        }
        __syncthreads();
        if (chunk + 3 < CHUNKS) load_stage(chunk + 3, s);
        s = (s == 2) ? 0 : s + 1;
    }

#pragma unroll
    for (int mt = 0; mt < 4; mt++) {
#pragma unroll
        for (int half = 0; half < 2; half++) {
            const int m = bm + warp_m * 64 + mt * 16 + (lane >> 2) + half * 8;
#pragma unroll
            for (int nt = 0; nt < 8; nt++) {
                const int n = bn + warp_n * 64 + nt * 8 + (lane & 3) * 2;
                const float v0 = acc[mt][nt][2 * half] * cscale;
                const float v1 = acc[mt][nt][2 * half + 1] * cscale;
                if (MODE == 0) {
                    const int b = m >> 11;
                    const int sq = m & 2047;
                    const int h = n >> 6;
                    const int dd = n & 63;
                    const size_t idx =
                        ((size_t)((b * NHEAD + h) * SEQ + sq) << 6) + dd;
                    uint32_t ph, pl;
                    split2(v0, v1, ph, pl);
                    *(uint32_t*)&Ch[idx] = ph;
                    *(uint32_t*)&Cl[idx] = pl;
                } else {
                    const size_t idx = (size_t)m * D_MODEL + n;
                    *(float2*)&Cf[idx] = make_float2(v0, v1);
                }
            }
        }
    }
}

__global__ void __launch_bounds__(256) gemm_qkv_kernel(
    const __nv_bfloat16* __restrict__ xh, const __nv_bfloat16* __restrict__ xl,
    const __nv_bfloat16* __restrict__ wqh, const __nv_bfloat16* __restrict__ wql,
    const __nv_bfloat16* __restrict__ wkh, const __nv_bfloat16* __restrict__ wkl,
    const __nv_bfloat16* __restrict__ wvh, const __nv_bfloat16* __restrict__ wvl,
    __nv_bfloat16* __restrict__ qh, __nv_bfloat16* __restrict__ ql,
    __nv_bfloat16* __restrict__ kh, __nv_bfloat16* __restrict__ kl,
    __nv_bfloat16* __restrict__ vh, __nv_bfloat16* __restrict__ vl)
{
    const int proj = blockIdx.x >> 3;
    const int bn = (blockIdx.x & 7) * BN;
    const int bm = blockIdx.y * BM;
    const __nv_bfloat16* Bh = (proj == 0) ? wqh : (proj == 1) ? wkh : wvh;
    const __nv_bfloat16* Bl = (proj == 0) ? wql : (proj == 1) ? wkl : wvl;
    __nv_bfloat16* Ch = (proj == 0) ? qh : (proj == 1) ? kh : vh;
    __nv_bfloat16* Cl = (proj == 0) ? ql : (proj == 1) ? kl : vl;
    const float cs = (proj == 0) ? QSCALE : 1.0f;   // fold 1/8*log2e into Q
    gemm_body<0>(xh, xl, Bh, Bl, Ch, Cl, nullptr, bm, bn, cs);
}

__global__ void __launch_bounds__(256) gemm_out_kernel(
    const __nv_bfloat16* __restrict__ ah, const __nv_bfloat16* __restrict__ al,
    const __nv_bfloat16* __restrict__ woh, const __nv_bfloat16* __restrict__ wol,
    float* __restrict__ out)
{
    gemm_body<1>(ah, al, woh, wol, nullptr, nullptr, out,
                 blockIdx.y * BM, blockIdx.x * BN, 1.0f);
}

// ---------------------------------------------------------------------------
// Tensor-core causal flash attention (R14 best — unchanged)
// ---------------------------------------------------------------------------
#define ATPAD 72
#define AT_STRIDE (ATPAD * 2)          // 144 bytes/row
#define AT_TILE_B (64 * AT_STRIDE)     // 9216
#define AT_STAGE_B (4 * AT_TILE_B)     // 36864 (Kh,Kl,Vh,Vl)
#define ATTN_SMEM (2 * AT_STAGE_B)     // 73728

__global__ void __launch_bounds__(128, 3) attn_mma_kernel(
    const __nv_bfloat16* __restrict__ Qh, const __nv_bfloat16* __restrict__ Ql,
    const __nv_bfloat16* __restrict__ Kh, const __nv_bfloat16* __restrict__ Kl,
    const __nv_bfloat16* __restrict__ Vh, const __nv_bfloat16* __restrict__ Vl,
    __nv_bfloat16* __restrict__ Ah, __nv_bfloat16* __restrict__ Al)
{
    extern __shared__ __align__(128) char smem[];
    const uint32_t sbase = smem_u32(smem);
    const int tid  = threadIdx.x;
    const int wid  = tid >> 5;
    const int lane = tid & 31;
    const int bh = blockIdx.y;
    const int qb = (int)gridDim.x - 1 - (int)blockIdx.x;   // heavy CTAs first
    const int q0 = qb * 64;
    const size_t base_off = (size_t)bh * SEQ * DKH;

#pragma unroll
    for (int u = 0; u < 8; u++) {
        const int id = u * 128 + tid;
        const int t = id >> 9;
        const int idx = id & 511;
        const int row = idx >> 3;
        const int c = idx & 7;
        const __nv_bfloat16* g = t ? Ql : Qh;
        CP_ASYNC16(sbase + t * AT_TILE_B + row * AT_STRIDE + c * 16,
                   g + base_off + (size_t)(q0 + row) * DKH + c * 8);
    }
    CP_COMMIT();
    CP_WAIT(0);
    __syncthreads();

    uint32_t Qh_[4][4], Ql_[4][4];
    {
        const uint32_t qa =
            sbase + (16 * wid + (lane & 15)) * AT_STRIDE + (lane >> 4) * 16;
#pragma unroll
        for (int ks = 0; ks < 4; ks++) {
            LDMATRIX_X4(Qh_[ks][0], Qh_[ks][1], Qh_[ks][2], Qh_[ks][3],
                        qa + ks * 32);
            LDMATRIX_X4(Ql_[ks][0], Ql_[ks][1], Ql_[ks][2], Ql_[ks][3],
                        qa + AT_TILE_B + ks * 32);
        }
    }
    __syncthreads();

    auto load_kv = [&](int jt, int buf) {
        const uint32_t st = sbase + buf * AT_STAGE_B;
        const int k0 = jt * 64;
#pragma unroll
        for (int u = 0; u < 16; u++) {
            const int id = u * 128 + tid;
            const int t = id >> 9;
            const int idx = id & 511;
            const int row = idx >> 3;
            const int c = idx & 7;
            const __nv_bfloat16* g = (t == 0) ? Kh : (t == 1) ? Kl
                                     : (t == 2) ? Vh : Vl;
            CP_ASYNC16(st + t * AT_TILE_B + row * AT_STRIDE + c * 16,
                       g + base_off + (size_t)(k0 + row) * DKH + c * 8);
        }
        CP_COMMIT();
    };

    float O_[8][4];
#pragma unroll
    for (int i = 0; i < 8; i++)
#pragma unroll
        for (int j = 0; j < 4; j++) O_[i][j] = 0.0f;
    float m_lo = -1e30f, m_hi = -1e30f;
    float l_lo = 0.0f, l_hi = 0.0f;     // per-lane partial sums (deferred red.)

    const int row_lo = q0 + 16 * wid + (lane >> 2);
    const int row_hi = row_lo + 8;
    const uint32_t b_off =
        (((lane >> 4) & 1) * 8 + (lane & 7)) * AT_STRIDE + ((lane >> 3) & 1) * 16;
    const uint32_t v_off = (lane & 15) * AT_STRIDE + (lane >> 4) * 16;

    const int jmax = qb;
    load_kv(0, 0);

    for (int jt = 0; jt <= jmax; jt++) {
        if (jt < jmax) { load_kv(jt + 1, (jt + 1) & 1); CP_WAIT(1); }
        else           { CP_WAIT(0); }
        __syncthreads();
        const uint32_t st = sbase + (jt & 1) * AT_STAGE_B;

        float S_[8][4];
#pragma unroll
        for (int i = 0; i < 8; i++)
#pragma unroll
            for (int j = 0; j < 4; j++) S_[i][j] = 0.0f;

#pragma unroll
        for (int ks = 0; ks < 4; ks++)
#pragma unroll
            for (int np = 0; np < 4; np++) {
                uint32_t f0, f1, f2, f3, g0, g1, g2, g3;
                const uint32_t ka = st + np * 16 * AT_STRIDE + b_off + ks * 32;
                LDMATRIX_X4(f0, f1, f2, f3, ka);
                LDMATRIX_X4(g0, g1, g2, g3, ka + AT_TILE_B);
                MMA16816(S_[2 * np], Qh_[ks][0], Qh_[ks][1], Qh_[ks][2],
                         Qh_[ks][3], f0, f1);
                MMA16816(S_[2 * np + 1], Qh_[ks][0], Qh_[ks][1], Qh_[ks][2],
                         Qh_[ks][3], f2, f3);
                MMA16816(S_[2 * np], Qh_[ks][0], Qh_[ks][1], Qh_[ks][2],
                         Qh_[ks][3], g0, g1);
                MMA16816(S_[2 * np + 1], Qh_[ks][0], Qh_[ks][1], Qh_[ks][2],
                         Qh_[ks][3], g2, g3);
                MMA16816(S_[2 * np], Ql_[ks][0], Ql_[ks][1], Ql_[ks][2],
                         Ql_[ks][3], f0, f1);
                MMA16816(S_[2 * np + 1], Ql_[ks][0], Ql_[ks][1], Ql_[ks][2],
                         Ql_[ks][3], f2, f3);
            }

        if (jt == jmax) {
            const int k0g = jt * 64;
#pragma unroll
            for (int nt = 0; nt < 8; nt++) {
                const int col = k0g + 8 * nt + 2 * (lane & 3);
                if (col     > row_lo) S_[nt][0] = -1e30f;
                if (col + 1 > row_lo) S_[nt][1] = -1e30f;
                if (col     > row_hi) S_[nt][2] = -1e30f;
                if (col + 1 > row_hi) S_[nt][3] = -1e30f;
            }
        }

        float rmax_lo = -1e30f, rmax_hi = -1e30f;
#pragma unroll
        for (int nt = 0; nt < 8; nt++) {
            rmax_lo = fmaxf(rmax_lo, fmaxf(S_[nt][0], S_[nt][1]));
            rmax_hi = fmaxf(rmax_hi, fmaxf(S_[nt][2], S_[nt][3]));
        }
        rmax_lo = fmaxf(rmax_lo, __shfl_xor_sync(0xffffffffu, rmax_lo, 1));
        rmax_lo = fmaxf(rmax_lo, __shfl_xor_sync(0xffffffffu, rmax_lo, 2));
        rmax_hi = fmaxf(rmax_hi, __shfl_xor_sync(0xffffffffu, rmax_hi, 1));
        rmax_hi = fmaxf(rmax_hi, __shfl_xor_sync(0xffffffffu, rmax_hi, 2));

        const float mn_lo = fmaxf(m_lo, rmax_lo);
        const float mn_hi = fmaxf(m_hi, rmax_hi);
        const float al_lo = ex2(m_lo - mn_lo);
        const float al_hi = ex2(m_hi - mn_hi);
        m_lo = mn_lo; m_hi = mn_hi;

        float rs_lo = 0.0f, rs_hi = 0.0f;
#pragma unroll
        for (int nt = 0; nt < 8; nt++) {
            S_[nt][0] = ex2(S_[nt][0] - m_lo);
            S_[nt][1] = ex2(S_[nt][1] - m_lo);
            S_[nt][2] = ex2(S_[nt][2] - m_hi);
            S_[nt][3] = ex2(S_[nt][3] - m_hi);
            rs_lo += S_[nt][0] + S_[nt][1];
            rs_hi += S_[nt][2] + S_[nt][3];
        }
        l_lo = l_lo * al_lo + rs_lo;
        l_hi = l_hi * al_hi + rs_hi;

#pragma unroll
        for (int nt = 0; nt < 8; nt++) {
            O_[nt][0] *= al_lo; O_[nt][1] *= al_lo;
            O_[nt][2] *= al_hi; O_[nt][3] *= al_hi;
        }

#pragma unroll
        for (int kp = 0; kp < 4; kp++) {
            uint32_t Ph[4], Pl[4];
            split2(S_[2 * kp][0],     S_[2 * kp][1],     Ph[0], Pl[0]);
            split2(S_[2 * kp][2],     S_[2 * kp][3],     Ph[1], Pl[1]);
            split2(S_[2 * kp + 1][0], S_[2 * kp + 1][1], Ph[2], Pl[2]);
            split2(S_[2 * kp + 1][2], S_[2 * kp + 1][3], Ph[3], Pl[3]);
#pragma unroll
            for (int dp = 0; dp < 4; dp++) {
                uint32_t v0, v1, v2, v3, w0, w1, w2, w3;
                const uint32_t va = st + 2 * AT_TILE_B +
                                    kp * 16 * AT_STRIDE + v_off + dp * 32;
                LDMATRIX_X4_T(v0, v1, v2, v3, va);
                LDMATRIX_X4_T(w0, w1, w2, w3, va + AT_TILE_B);
                MMA16816(O_[2 * dp], Ph[0], Ph[1], Ph[2], Ph[3], v0, v1);
                MMA16816(O_[2 * dp + 1], Ph[0], Ph[1], Ph[2], Ph[3], v2, v3);
                MMA16816(O_[2 * dp], Ph[0], Ph[1], Ph[2], Ph[3], w0, w1);
                MMA16816(O_[2 * dp + 1], Ph[0], Ph[1], Ph[2], Ph[3], w2, w3);
                MMA16816(O_[2 * dp], Pl[0], Pl[1], Pl[2], Pl[3], v0, v1);
                MMA16816(O_[2 * dp + 1], Pl[0], Pl[1], Pl[2], Pl[3], v2, v3);
            }
        }
        __syncthreads();
    }

    l_lo += __shfl_xor_sync(0xffffffffu, l_lo, 1);
    l_lo += __shfl_xor_sync(0xffffffffu, l_lo, 2);
    l_hi += __shfl_xor_sync(0xffffffffu, l_hi, 1);
    l_hi += __shfl_xor_sync(0xffffffffu, l_hi, 2);
    const float inv_lo = 1.0f / l_lo;
    const float inv_hi = 1.0f / l_hi;
    const int b = bh >> 4;
    const int hh = bh & 15;
#pragma unroll
    for (int nt = 0; nt < 8; nt++) {
        const int col = hh * DKH + 8 * nt + 2 * (lane & 3);
        uint32_t ph, pl;
        split2(O_[nt][0] * inv_lo, O_[nt][1] * inv_lo, ph, pl);
        const size_t i0 = (size_t)(b * SEQ + row_lo) * D_MODEL + col;
        *(uint32_t*)&Ah[i0] = ph;
        *(uint32_t*)&Al[i0] = pl;
        split2(O_[nt][2] * inv_hi, O_[nt][3] * inv_hi, ph, pl);
        const size_t i1 = (size_t)(b * SEQ + row_hi) * D_MODEL + col;
        *(uint32_t*)&Ah[i1] = ph;
        *(uint32_t*)&Al[i1] = pl;
    }
}

// ---------------------------------------------------------------------------
// launch
// ---------------------------------------------------------------------------
extern "C" void kernel_launch(void* const* d_in, const int* in_sizes, int n_in,
                              void* d_out, int out_size)
{
    (void)in_sizes; (void)n_in; (void)out_size;
    const float* x  = (const float*)d_in[0];
    const float* wq = (const float*)d_in[1];
    const float* wk = (const float*)d_in[2];
    const float* wv = (const float*)d_in[3];
    const float* wo = (const float*)d_in[4];
    float* out = (float*)d_out;

    __nv_bfloat16 *xh, *xl, *qh, *ql, *kh, *kl, *vh, *vl, *ah, *al;
    __nv_bfloat16 *wqh, *wql, *wkh, *wkl, *wvh, *wvl, *woh, *wol;
    cudaGetSymbolAddress((void**)&xh, g_xh);
    cudaGetSymbolAddress((void**)&xl, g_xl);
    cudaGetSymbolAddress((void**)&qh, g_qh);
    cudaGetSymbolAddress((void**)&ql, g_ql);
    cudaGetSymbolAddress((void**)&kh, g_kh);
    cudaGetSymbolAddress((void**)&kl, g_kl);
    cudaGetSymbolAddress((void**)&vh, g_vh);
    cudaGetSymbolAddress((void**)&vl, g_vl);
    cudaGetSymbolAddress((void**)&ah, g_ah);
    cudaGetSymbolAddress((void**)&al, g_al);
    cudaGetSymbolAddress((void**)&wqh, g_wqh);
    cudaGetSymbolAddress((void**)&wql, g_wql);
    cudaGetSymbolAddress((void**)&wkh, g_wkh);
    cudaGetSymbolAddress((void**)&wkl, g_wkl);
    cudaGetSymbolAddress((void**)&wvh, g_wvh);
    cudaGetSymbolAddress((void**)&wvl, g_wvl);
    cudaGetSymbolAddress((void**)&woh, g_woh);
    cudaGetSymbolAddress((void**)&wol, g_wol);

    cudaFuncSetAttribute(gemm_qkv_kernel,
                         cudaFuncAttributeMaxDynamicSharedMemorySize, GEMM_SMEM);
    cudaFuncSetAttribute(gemm_out_kernel,
                         cudaFuncAttributeMaxDynamicSharedMemorySize, GEMM_SMEM);
    cudaFuncSetAttribute(attn_mma_kernel,
                         cudaFuncAttributeMaxDynamicSharedMemorySize, ATTN_SMEM);

    const int nx4 = MTOK * D_MODEL / 4;
    split_kernel<<<(nx4 + 255) / 256, 256>>>(x, xh, xl, nx4);
    split4_kernel<<<(4 * NW4 + 255) / 256, 256>>>(
        wq, wk, wv, wo, wqh, wql, wkh, wkl, wvh, wvl, woh, wol);

    gemm_qkv_kernel<<<dim3(24, MTOK / BM), 256, GEMM_SMEM>>>(
        xh, xl, wqh, wql, wkh, wkl, wvh, wvl, qh, ql, kh, kl, vh, vl);

    attn_mma_kernel<<<dim3(SEQ / 64, BATCH * NHEAD), 128, ATTN_SMEM>>>(
        qh, ql, kh, kl, vh, vl, ah, al);

    gemm_out_kernel<<<dim3(D_MODEL / BN, MTOK / BM), 256, GEMM_SMEM>>>(
        ah, al, woh, wol, out);
}

// round 16
// speedup vs baseline: 1.1106x; 1.1106x over previous
#include <cuda_runtime.h>
#include <cuda_bf16.h>
#include <cstdint>
#include <math.h>

#define D_MODEL 1024
#define NHEAD 16
#define DKH 64
#define BATCH 4
#define SEQ 2048
#define MTOK (BATCH * SEQ)   // 8192

// 0.125 * log2(e): folded into Q so attention scores are exp2-ready
#define QSCALE 0.18033688011112042f

// ---------------------------------------------------------------------------
// Scratch (alloc-free rule: __device__ globals)
// ---------------------------------------------------------------------------
__device__ __nv_bfloat16 g_xh[MTOK * D_MODEL];
__device__ __nv_bfloat16 g_xl[MTOK * D_MODEL];
__device__ __nv_bfloat16 g_qh[MTOK * D_MODEL];   // [B,H,S,64] (pre-scaled)
__device__ __nv_bfloat16 g_ql[MTOK * D_MODEL];
__device__ __nv_bfloat16 g_kh[MTOK * D_MODEL];
__device__ __nv_bfloat16 g_kl[MTOK * D_MODEL];
__device__ __nv_bfloat16 g_vh[MTOK * D_MODEL];
__device__ __nv_bfloat16 g_vl[MTOK * D_MODEL];
__device__ __nv_bfloat16 g_ah[MTOK * D_MODEL];   // attn out [B,S,D]
__device__ __nv_bfloat16 g_al[MTOK * D_MODEL];
__device__ __nv_bfloat16 g_wqh[D_MODEL * D_MODEL];
__device__ __nv_bfloat16 g_wql[D_MODEL * D_MODEL];
__device__ __nv_bfloat16 g_wkh[D_MODEL * D_MODEL];
__device__ __nv_bfloat16 g_wkl[D_MODEL * D_MODEL];
__device__ __nv_bfloat16 g_wvh[D_MODEL * D_MODEL];
__device__ __nv_bfloat16 g_wvl[D_MODEL * D_MODEL];
__device__ __nv_bfloat16 g_woh[D_MODEL * D_MODEL];
__device__ __nv_bfloat16 g_wol[D_MODEL * D_MODEL];

// ---------------------------------------------------------------------------
// helpers (arch-portable only: cp.async / ldmatrix / mma.sync)
// ---------------------------------------------------------------------------
__device__ __forceinline__ uint32_t smem_u32(const void* p) {
    uint32_t a;
    asm("{ .reg .u64 t; cvta.to.shared.u64 t, %1; cvt.u32.u64 %0, t; }"
        : "=r"(a) : "l"(p));
    return a;
}

#define LDMATRIX_X4(r0, r1, r2, r3, addr) \
    asm volatile("ldmatrix.sync.aligned.m8n8.x4.shared.b16 {%0,%1,%2,%3}, [%4];" \
        : "=r"(r0), "=r"(r1), "=r"(r2), "=r"(r3) : "r"(addr))

#define LDMATRIX_X4_T(r0, r1, r2, r3, addr) \
    asm volatile("ldmatrix.sync.aligned.m8n8.x4.trans.shared.b16 {%0,%1,%2,%3}, [%4];" \
        : "=r"(r0), "=r"(r1), "=r"(r2), "=r"(r3) : "r"(addr))

#define MMA16816(d, a0, a1, a2, a3, b0, b1) \
    asm volatile("mma.sync.aligned.m16n8k16.row.col.f32.bf16.bf16.f32 " \
        "{%0,%1,%2,%3}, {%4,%5,%6,%7}, {%8,%9}, {%0,%1,%2,%3};" \
        : "+f"((d)[0]), "+f"((d)[1]), "+f"((d)[2]), "+f"((d)[3]) \
        : "r"(a0), "r"(a1), "r"(a2), "r"(a3), "r"(b0), "r"(b1))

#define CP_ASYNC16(saddr, gaddr) \
    asm volatile("cp.async.cg.shared.global [%0], [%1], 16;" \
        :: "r"(saddr), "l"(gaddr))
#define CP_COMMIT() asm volatile("cp.async.commit_group;" ::: "memory")
#define CP_WAIT(n)  asm volatile("cp.async.wait_group %0;" :: "n"(n) : "memory")

#define PACK_BF16X2(r, lo, hi) \
    asm("cvt.rn.bf16x2.f32 %0, %1, %2;" : "=r"(r) : "f"(hi), "f"(lo))

__device__ __forceinline__ void split2(float v0, float v1,
                                       uint32_t& ph, uint32_t& pl) {
    PACK_BF16X2(ph, v0, v1);
    const float f0 = __uint_as_float(ph << 16);
    const float f1 = __uint_as_float(ph & 0xffff0000u);
    PACK_BF16X2(pl, v0 - f0, v1 - f1);
}

__device__ __forceinline__ float ex2(float x) {
    float y;
    asm("ex2.approx.f32 %0, %1;" : "=f"(y) : "f"(x));
    return y;
}

// ---------------------------------------------------------------------------
// fused fp32 -> bf16 hi/lo split: x (2M float4) + 4 weights (256K float4 each)
// ---------------------------------------------------------------------------
#define NX4 (MTOK * D_MODEL / 4)       // 2097152
#define NW4 (D_MODEL * D_MODEL / 4)    // 262144
#define NSPLIT4 (NX4 + 4 * NW4)        // 3145728

__global__ void __launch_bounds__(256) split_all_kernel(
    const float* __restrict__ x,
    const float* __restrict__ w0, const float* __restrict__ w1,
    const float* __restrict__ w2, const float* __restrict__ w3,
    __nv_bfloat16* __restrict__ xh, __nv_bfloat16* __restrict__ xl,
    __nv_bfloat16* __restrict__ h0, __nv_bfloat16* __restrict__ l0,
    __nv_bfloat16* __restrict__ h1, __nv_bfloat16* __restrict__ l1,
    __nv_bfloat16* __restrict__ h2, __nv_bfloat16* __restrict__ l2,
    __nv_bfloat16* __restrict__ h3, __nv_bfloat16* __restrict__ l3)
{
    const int id = blockIdx.x * 256 + threadIdx.x;
    if (id >= NSPLIT4) return;
    const float* in;
    __nv_bfloat16 *hi, *lo;
    int i;
    if (id < NX4) {
        in = x; hi = xh; lo = xl; i = id;
    } else {
        const int r = id - NX4;
        const int which = r / NW4;
        i = r - which * NW4;
        in = (which == 0) ? w0 : (which == 1) ? w1 : (which == 2) ? w2 : w3;
        hi = (which == 0) ? h0 : (which == 1) ? h1 : (which == 2) ? h2 : h3;
        lo = (which == 0) ? l0 : (which == 1) ? l1 : (which == 2) ? l2 : l3;
    }
    float4 v = ((const float4*)in)[i];
    uint32_t h01, l01, h23, l23;
    split2(v.x, v.y, h01, l01);
    split2(v.z, v.w, h23, l23);
    ((uint32_t*)hi)[2 * i]     = h01;
    ((uint32_t*)hi)[2 * i + 1] = h23;
    ((uint32_t*)lo)[2 * i]     = l01;
    ((uint32_t*)lo)[2 * i + 1] = l23;
}

// ---------------------------------------------------------------------------
// mma.sync bf16 3-pass GEMM body (R10/R14 config — proven best)
// 128x128 tile/CTA, BK=32, XOR swizzle, 3-stage pipeline, 2 CTAs/SM.
// ---------------------------------------------------------------------------
#define BM 128
#define BN 128
#define BK 32
#define CHUNKS (D_MODEL / BK)          // 32
#define TILE_B (128 * 64)              // 8192 bytes, swizzled
#define STAGE_B (4 * TILE_B)           // 32768 (Ah,Al,Bh,Bl)
#define GEMM_SMEM (3 * STAGE_B)        // 98304

template <int MODE>
__device__ __forceinline__ void gemm_body(
    const __nv_bfloat16* __restrict__ Ah, const __nv_bfloat16* __restrict__ Al,
    const __nv_bfloat16* __restrict__ Bh, const __nv_bfloat16* __restrict__ Bl,
    __nv_bfloat16* __restrict__ Ch, __nv_bfloat16* __restrict__ Cl,
    float* __restrict__ Cf, const int bm, const int bn, const float cscale)
{
    extern __shared__ __align__(128) char smem[];
    const uint32_t sbase = smem_u32(smem);
    const int tid  = threadIdx.x;
    const int wid  = tid >> 5;
    const int lane = tid & 31;
    const int K = D_MODEL;

    const int warp_m = wid >> 2;
    const int warp_n = wid & 3;

    auto load_stage = [&](int chunk, int s) {
        const uint32_t st = sbase + s * STAGE_B;
        const int k0 = chunk * BK;
#pragma unroll
        for (int u = 0; u < 8; u++) {
            const int id = u * 256 + tid;
            const int t = id >> 9;
            const int idx = id & 511;
            const int row = idx >> 2;
            const int c = idx & 3;
            const __nv_bfloat16* g;
            int grow;
            if (t == 0)      { g = Ah; grow = bm + row; }
            else if (t == 1) { g = Al; grow = bm + row; }
            else if (t == 2) { g = Bh; grow = bn + row; }
            else             { g = Bl; grow = bn + row; }
            const __nv_bfloat16* gaddr = g + (size_t)grow * K + k0 + c * 8;
            const uint32_t saddr = st + t * TILE_B + row * 64 +
                                   (((uint32_t)(c ^ ((row >> 1) & 3))) << 4);
            CP_ASYNC16(saddr, gaddr);
        }
        CP_COMMIT();
    };

    load_stage(0, 0);
    load_stage(1, 1);
    load_stage(2, 2);

    float acc[4][4][4];
#pragma unroll
    for (int i = 0; i < 4; i++)
#pragma unroll
        for (int j = 0; j < 4; j++)
#pragma unroll
            for (int r = 0; r < 4; r++) acc[i][j][r] = 0.0f;

    const int a_row = warp_m * 64 + (lane & 15);
    const uint32_t a_off = (uint32_t)a_row * 64 +
        ((uint32_t)(((lane >> 4) ^ ((a_row >> 1) & 3))) << 4);
    const int b_row = warp_n * 32 + ((lane >> 4) & 1) * 8 + (lane & 7);
    const uint32_t b_off = (uint32_t)b_row * 64 +
        ((uint32_t)((((lane >> 3) & 1) ^ ((b_row >> 1) & 3))) << 4);

    int s = 0;
    for (int chunk = 0; chunk < CHUNKS; chunk++) {
        if (chunk < CHUNKS - 2)       CP_WAIT(2);
        else if (chunk == CHUNKS - 2) CP_WAIT(1);
        else                          CP_WAIT(0);
        __syncthreads();
        const uint32_t st = sbase + s * STAGE_B;
        const uint32_t aH = st + a_off;
        const uint32_t aL = st + TILE_B + a_off;
        const uint32_t bH = st + 2 * TILE_B + b_off;
        const uint32_t bL = st + 3 * TILE_B + b_off;

#pragma unroll
        for (int ks = 0; ks < 2; ks++) {
            const uint32_t kx = (uint32_t)ks << 5;
            uint32_t fAH[4][4], fAL[4][4], fBH[4][2], fBL[4][2];
#pragma unroll
            for (int mt = 0; mt < 4; mt++) {
                LDMATRIX_X4(fAH[mt][0], fAH[mt][1], fAH[mt][2], fAH[mt][3],
                            (aH + mt * 1024) ^ kx);
                LDMATRIX_X4(fAL[mt][0], fAL[mt][1], fAL[mt][2], fAL[mt][3],
                            (aL + mt * 1024) ^ kx);
            }
#pragma unroll
            for (int np = 0; np < 2; np++) {
                LDMATRIX_X4(fBH[2 * np][0], fBH[2 * np][1],
                            fBH[2 * np + 1][0], fBH[2 * np + 1][1],
                            (bH + np * 1024) ^ kx);
                LDMATRIX_X4(fBL[2 * np][0], fBL[2 * np][1],
                            fBL[2 * np + 1][0], fBL[2 * np + 1][1],
                            (bL + np * 1024) ^ kx);
            }
#pragma unroll
            for (int mt = 0; mt < 4; mt++)
#pragma unroll
                for (int nt = 0; nt < 4; nt++) {
                    MMA16816(acc[mt][nt], fAH[mt][0], fAH[mt][1], fAH[mt][2],
                             fAH[mt][3], fBH[nt][0], fBH[nt][1]);
                    MMA16816(acc[mt][nt], fAH[mt][0], fAH[mt][1], fAH[mt][2],
                             fAH[mt][3], fBL[nt][0], fBL[nt][1]);
                    MMA16816(acc[mt][nt], fAL[mt][0], fAL[mt][1], fAL[mt][2],
                             fAL[mt][3], fBH[nt][0], fBH[nt][1]);
                }
        }
        __syncthreads();
        if (chunk + 3 < CHUNKS) load_stage(chunk + 3, s);
        s = (s == 2) ? 0 : s + 1;
    }

#pragma unroll
    for (int mt = 0; mt < 4; mt++) {
#pragma unroll
        for (int half = 0; half < 2; half++) {
            const int m = bm + warp_m * 64 + mt * 16 + (lane >> 2) + half * 8;
#pragma unroll
            for (int nt = 0; nt < 4; nt++) {
                const int n = bn + warp_n * 32 + nt * 8 + (lane & 3) * 2;
                const float v0 = acc[mt][nt][2 * half] * cscale;
                const float v1 = acc[mt][nt][2 * half + 1] * cscale;
                if (MODE == 0) {
                    const int b = m >> 11;
                    const int sq = m & 2047;
                    const int h = n >> 6;
                    const int dd = n & 63;
                    const size_t idx =
                        ((size_t)((b * NHEAD + h) * SEQ + sq) << 6) + dd;
                    uint32_t ph, pl;
                    split2(v0, v1, ph, pl);
                    *(uint32_t*)&Ch[idx] = ph;
                    *(uint32_t*)&Cl[idx] = pl;
                } else {
                    const size_t idx = (size_t)m * D_MODEL + n;
                    *(float2*)&Cf[idx] = make_float2(v0, v1);
                }
            }
        }
    }
}

__global__ void __launch_bounds__(256, 2) gemm_qkv_kernel(
    const __nv_bfloat16* __restrict__ xh, const __nv_bfloat16* __restrict__ xl,
    const __nv_bfloat16* __restrict__ wqh, const __nv_bfloat16* __restrict__ wql,
    const __nv_bfloat16* __restrict__ wkh, const __nv_bfloat16* __restrict__ wkl,
    const __nv_bfloat16* __restrict__ wvh, const __nv_bfloat16* __restrict__ wvl,
    __nv_bfloat16* __restrict__ qh, __nv_bfloat16* __restrict__ ql,
    __nv_bfloat16* __restrict__ kh, __nv_bfloat16* __restrict__ kl,
    __nv_bfloat16* __restrict__ vh, __nv_bfloat16* __restrict__ vl)
{
    const int proj = blockIdx.x >> 3;
    const int bn = (blockIdx.x & 7) * BN;
    const int bm = blockIdx.y * BM;
    const __nv_bfloat16* Bh = (proj == 0) ? wqh : (proj == 1) ? wkh : wvh;
    const __nv_bfloat16* Bl = (proj == 0) ? wql : (proj == 1) ? wkl : wvl;
    __nv_bfloat16* Ch = (proj == 0) ? qh : (proj == 1) ? kh : vh;
    __nv_bfloat16* Cl = (proj == 0) ? ql : (proj == 1) ? kl : vl;
    const float cs = (proj == 0) ? QSCALE : 1.0f;   // fold 1/8*log2e into Q
    gemm_body<0>(xh, xl, Bh, Bl, Ch, Cl, nullptr, bm, bn, cs);
}

__global__ void __launch_bounds__(256, 2) gemm_out_kernel(
    const __nv_bfloat16* __restrict__ ah, const __nv_bfloat16* __restrict__ al,
    const __nv_bfloat16* __restrict__ woh, const __nv_bfloat16* __restrict__ wol,
    float* __restrict__ out)
{
    gemm_body<1>(ah, al, woh, wol, nullptr, nullptr, out,
                 blockIdx.y * BM, blockIdx.x * BN, 1.0f);
}

// ---------------------------------------------------------------------------
// Tensor-core causal flash attention (R14 best — unchanged)
// ---------------------------------------------------------------------------
#define ATPAD 72
#define AT_STRIDE (ATPAD * 2)          // 144 bytes/row
#define AT_TILE_B (64 * AT_STRIDE)     // 9216
#define AT_STAGE_B (4 * AT_TILE_B)     // 36864 (Kh,Kl,Vh,Vl)
#define ATTN_SMEM (2 * AT_STAGE_B)     // 73728

__global__ void __launch_bounds__(128, 3) attn_mma_kernel(
    const __nv_bfloat16* __restrict__ Qh, const __nv_bfloat16* __restrict__ Ql,
    const __nv_bfloat16* __restrict__ Kh, const __nv_bfloat16* __restrict__ Kl,
    const __nv_bfloat16* __restrict__ Vh, const __nv_bfloat16* __restrict__ Vl,
    __nv_bfloat16* __restrict__ Ah, __nv_bfloat16* __restrict__ Al)
{
    extern __shared__ __align__(128) char smem[];
    const uint32_t sbase = smem_u32(smem);
    const int tid  = threadIdx.x;
    const int wid  = tid >> 5;
    const int lane = tid & 31;
    const int bh = blockIdx.y;
    const int qb = (int)gridDim.x - 1 - (int)blockIdx.x;   // heavy CTAs first
    const int q0 = qb * 64;
    const size_t base_off = (size_t)bh * SEQ * DKH;

#pragma unroll
    for (int u = 0; u < 8; u++) {
        const int id = u * 128 + tid;
        const int t = id >> 9;
        const int idx = id & 511;
        const int row = idx >> 3;
        const int c = idx & 7;
        const __nv_bfloat16* g = t ? Ql : Qh;
        CP_ASYNC16(sbase + t * AT_TILE_B + row * AT_STRIDE + c * 16,
                   g + base_off + (size_t)(q0 + row) * DKH + c * 8);
    }
    CP_COMMIT();
    CP_WAIT(0);
    __syncthreads();

    uint32_t Qh_[4][4], Ql_[4][4];
    {
        const uint32_t qa =
            sbase + (16 * wid + (lane & 15)) * AT_STRIDE + (lane >> 4) * 16;
#pragma unroll
        for (int ks = 0; ks < 4; ks++) {
            LDMATRIX_X4(Qh_[ks][0], Qh_[ks][1], Qh_[ks][2], Qh_[ks][3],
                        qa + ks * 32);
            LDMATRIX_X4(Ql_[ks][0], Ql_[ks][1], Ql_[ks][2], Ql_[ks][3],
                        qa + AT_TILE_B + ks * 32);
        }
    }
    __syncthreads();

    auto load_kv = [&](int jt, int buf) {
        const uint32_t st = sbase + buf * AT_STAGE_B;
        const int k0 = jt * 64;
#pragma unroll
        for (int u = 0; u < 16; u++) {
            const int id = u * 128 + tid;
            const int t = id >> 9;
            const int idx = id & 511;
            const int row = idx >> 3;
            const int c = idx & 7;
            const __nv_bfloat16* g = (t == 0) ? Kh : (t == 1) ? Kl
                                     : (t == 2) ? Vh : Vl;
            CP_ASYNC16(st + t * AT_TILE_B + row * AT_STRIDE + c * 16,
                       g + base_off + (size_t)(k0 + row) * DKH + c * 8);
        }
        CP_COMMIT();
    };

    float O_[8][4];
#pragma unroll
    for (int i = 0; i < 8; i++)
#pragma unroll
        for (int j = 0; j < 4; j++) O_[i][j] = 0.0f;
    float m_lo = -1e30f, m_hi = -1e30f;
    float l_lo = 0.0f, l_hi = 0.0f;     // per-lane partial sums (deferred red.)

    const int row_lo = q0 + 16 * wid + (lane >> 2);
    const int row_hi = row_lo + 8;
    const uint32_t b_off =
        (((lane >> 4) & 1) * 8 + (lane & 7)) * AT_STRIDE + ((lane >> 3) & 1) * 16;
    const uint32_t v_off = (lane & 15) * AT_STRIDE + (lane >> 4) * 16;

    const int jmax = qb;
    load_kv(0, 0);

    for (int jt = 0; jt <= jmax; jt++) {
        if (jt < jmax) { load_kv(jt + 1, (jt + 1) & 1); CP_WAIT(1); }
        else           { CP_WAIT(0); }
        __syncthreads();
        const uint32_t st = sbase + (jt & 1) * AT_STAGE_B;

        float S_[8][4];
#pragma unroll
        for (int i = 0; i < 8; i++)
#pragma unroll
            for (int j = 0; j < 4; j++) S_[i][j] = 0.0f;

#pragma unroll
        for (int ks = 0; ks < 4; ks++)
#pragma unroll
            for (int np = 0; np < 4; np++) {
                uint32_t f0, f1, f2, f3, g0, g1, g2, g3;
                const uint32_t ka = st + np * 16 * AT_STRIDE + b_off + ks * 32;
                LDMATRIX_X4(f0, f1, f2, f3, ka);
                LDMATRIX_X4(g0, g1, g2, g3, ka + AT_TILE_B);
                MMA16816(S_[2 * np], Qh_[ks][0], Qh_[ks][1], Qh_[ks][2],
                         Qh_[ks][3], f0, f1);
                MMA16816(S_[2 * np + 1], Qh_[ks][0], Qh_[ks][1], Qh_[ks][2],
                         Qh_[ks][3], f2, f3);
                MMA16816(S_[2 * np], Qh_[ks][0], Qh_[ks][1], Qh_[ks][2],
                         Qh_[ks][3], g0, g1);
                MMA16816(S_[2 * np + 1], Qh_[ks][0], Qh_[ks][1], Qh_[ks][2],
                         Qh_[ks][3], g2, g3);
                MMA16816(S_[2 * np], Ql_[ks][0], Ql_[ks][1], Ql_[ks][2],
                         Ql_[ks][3], f0, f1);
                MMA16816(S_[2 * np + 1], Ql_[ks][0], Ql_[ks][1], Ql_[ks][2],
                         Ql_[ks][3], f2, f3);
            }

        if (jt == jmax) {
            const int k0g = jt * 64;
#pragma unroll
            for (int nt = 0; nt < 8; nt++) {
                const int col = k0g + 8 * nt + 2 * (lane & 3);
                if (col     > row_lo) S_[nt][0] = -1e30f;
                if (col + 1 > row_lo) S_[nt][1] = -1e30f;
                if (col     > row_hi) S_[nt][2] = -1e30f;
                if (col + 1 > row_hi) S_[nt][3] = -1e30f;
            }
        }

        float rmax_lo = -1e30f, rmax_hi = -1e30f;
#pragma unroll
        for (int nt = 0; nt < 8; nt++) {
            rmax_lo = fmaxf(rmax_lo, fmaxf(S_[nt][0], S_[nt][1]));
            rmax_hi = fmaxf(rmax_hi, fmaxf(S_[nt][2], S_[nt][3]));
        }
        rmax_lo = fmaxf(rmax_lo, __shfl_xor_sync(0xffffffffu, rmax_lo, 1));
        rmax_lo = fmaxf(rmax_lo, __shfl_xor_sync(0xffffffffu, rmax_lo, 2));
        rmax_hi = fmaxf(rmax_hi, __shfl_xor_sync(0xffffffffu, rmax_hi, 1));
        rmax_hi = fmaxf(rmax_hi, __shfl_xor_sync(0xffffffffu, rmax_hi, 2));

        const float mn_lo = fmaxf(m_lo, rmax_lo);
        const float mn_hi = fmaxf(m_hi, rmax_hi);
        const float al_lo = ex2(m_lo - mn_lo);
        const float al_hi = ex2(m_hi - mn_hi);
        m_lo = mn_lo; m_hi = mn_hi;

        float rs_lo = 0.0f, rs_hi = 0.0f;
#pragma unroll
        for (int nt = 0; nt < 8; nt++) {
            S_[nt][0] = ex2(S_[nt][0] - m_lo);
            S_[nt][1] = ex2(S_[nt][1] - m_lo);
            S_[nt][2] = ex2(S_[nt][2] - m_hi);
            S_[nt][3] = ex2(S_[nt][3] - m_hi);
            rs_lo += S_[nt][0] + S_[nt][1];
            rs_hi += S_[nt][2] + S_[nt][3];
        }
        l_lo = l_lo * al_lo + rs_lo;
        l_hi = l_hi * al_hi + rs_hi;

#pragma unroll
        for (int nt = 0; nt < 8; nt++) {
            O_[nt][0] *= al_lo; O_[nt][1] *= al_lo;
            O_[nt][2] *= al_hi; O_[nt][3] *= al_hi;
        }

#pragma unroll
        for (int kp = 0; kp < 4; kp++) {
            uint32_t Ph[4], Pl[4];
            split2(S_[2 * kp][0],     S_[2 * kp][1],     Ph[0], Pl[0]);
            split2(S_[2 * kp][2],     S_[2 * kp][3],     Ph[1], Pl[1]);
            split2(S_[2 * kp + 1][0], S_[2 * kp + 1][1], Ph[2], Pl[2]);
            split2(S_[2 * kp + 1][2], S_[2 * kp + 1][3], Ph[3], Pl[3]);
#pragma unroll
            for (int dp = 0; dp < 4; dp++) {
                uint32_t v0, v1, v2, v3, w0, w1, w2, w3;
                const uint32_t va = st + 2 * AT_TILE_B +
                                    kp * 16 * AT_STRIDE + v_off + dp * 32;
                LDMATRIX_X4_T(v0, v1, v2, v3, va);
                LDMATRIX_X4_T(w0, w1, w2, w3, va + AT_TILE_B);
                MMA16816(O_[2 * dp], Ph[0], Ph[1], Ph[2], Ph[3], v0, v1);
                MMA16816(O_[2 * dp + 1], Ph[0], Ph[1], Ph[2], Ph[3], v2, v3);
                MMA16816(O_[2 * dp], Ph[0], Ph[1], Ph[2], Ph[3], w0, w1);
                MMA16816(O_[2 * dp + 1], Ph[0], Ph[1], Ph[2], Ph[3], w2, w3);
                MMA16816(O_[2 * dp], Pl[0], Pl[1], Pl[2], Pl[3], v0, v1);
                MMA16816(O_[2 * dp + 1], Pl[0], Pl[1], Pl[2], Pl[3], v2, v3);
            }
        }
        __syncthreads();
    }

    l_lo += __shfl_xor_sync(0xffffffffu, l_lo, 1);
    l_lo += __shfl_xor_sync(0xffffffffu, l_lo, 2);
    l_hi += __shfl_xor_sync(0xffffffffu, l_hi, 1);
    l_hi += __shfl_xor_sync(0xffffffffu, l_hi, 2);
    const float inv_lo = 1.0f / l_lo;
    const float inv_hi = 1.0f / l_hi;
    const int b = bh >> 4;
    const int hh = bh & 15;
#pragma unroll
    for (int nt = 0; nt < 8; nt++) {
        const int col = hh * DKH + 8 * nt + 2 * (lane & 3);
        uint32_t ph, pl;
        split2(O_[nt][0] * inv_lo, O_[nt][1] * inv_lo, ph, pl);
        const size_t i0 = (size_t)(b * SEQ + row_lo) * D_MODEL + col;
        *(uint32_t*)&Ah[i0] = ph;
        *(uint32_t*)&Al[i0] = pl;
        split2(O_[nt][2] * inv_hi, O_[nt][3] * inv_hi, ph, pl);
        const size_t i1 = (size_t)(b * SEQ + row_hi) * D_MODEL + col;
        *(uint32_t*)&Ah[i1] = ph;
        *(uint32_t*)&Al[i1] = pl;
    }
}

// ---------------------------------------------------------------------------
// launch
// ---------------------------------------------------------------------------
extern "C" void kernel_launch(void* const* d_in, const int* in_sizes, int n_in,
                              void* d_out, int out_size)
{
    (void)in_sizes; (void)n_in; (void)out_size;
    const float* x  = (const float*)d_in[0];
    const float* wq = (const float*)d_in[1];
    const float* wk = (const float*)d_in[2];
    const float* wv = (const float*)d_in[3];
    const float* wo = (const float*)d_in[4];
    float* out = (float*)d_out;

    __nv_bfloat16 *xh, *xl, *qh, *ql, *kh, *kl, *vh, *vl, *ah, *al;
    __nv_bfloat16 *wqh, *wql, *wkh, *wkl, *wvh, *wvl, *woh, *wol;
    cudaGetSymbolAddress((void**)&xh, g_xh);
    cudaGetSymbolAddress((void**)&xl, g_xl);
    cudaGetSymbolAddress((void**)&qh, g_qh);
    cudaGetSymbolAddress((void**)&ql, g_ql);
    cudaGetSymbolAddress((void**)&kh, g_kh);
    cudaGetSymbolAddress((void**)&kl, g_kl);
    cudaGetSymbolAddress((void**)&vh, g_vh);
    cudaGetSymbolAddress((void**)&vl, g_vl);
    cudaGetSymbolAddress((void**)&ah, g_ah);
    cudaGetSymbolAddress((void**)&al, g_al);
    cudaGetSymbolAddress((void**)&wqh, g_wqh);
    cudaGetSymbolAddress((void**)&wql, g_wql);
    cudaGetSymbolAddress((void**)&wkh, g_wkh);
    cudaGetSymbolAddress((void**)&wkl, g_wkl);
    cudaGetSymbolAddress((void**)&wvh, g_wvh);
    cudaGetSymbolAddress((void**)&wvl, g_wvl);
    cudaGetSymbolAddress((void**)&woh, g_woh);
    cudaGetSymbolAddress((void**)&wol, g_wol);

    cudaFuncSetAttribute(gemm_qkv_kernel,
                         cudaFuncAttributeMaxDynamicSharedMemorySize, GEMM_SMEM);
    cudaFuncSetAttribute(gemm_out_kernel,
                         cudaFuncAttributeMaxDynamicSharedMemorySize, GEMM_SMEM);
    cudaFuncSetAttribute(attn_mma_kernel,
                         cudaFuncAttributeMaxDynamicSharedMemorySize, ATTN_SMEM);

    split_all_kernel<<<(NSPLIT4 + 255) / 256, 256>>>(
        x, wq, wk, wv, wo, xh, xl,
        wqh, wql, wkh, wkl, wvh, wvl, woh, wol);

    gemm_qkv_kernel<<<dim3(24, MTOK / BM), 256, GEMM_SMEM>>>(
        xh, xl, wqh, wql, wkh, wkl, wvh, wvl, qh, ql, kh, kl, vh, vl);

    attn_mma_kernel<<<dim3(SEQ / 64, BATCH * NHEAD), 128, ATTN_SMEM>>>(
        qh, ql, kh, kl, vh, vl, ah, al);

    gemm_out_kernel<<<dim3(D_MODEL / BN, MTOK / BM), 256, GEMM_SMEM>>>(
        ah, al, woh, wol, out);
}

// round 17
// speedup vs baseline: 1.1231x; 1.0112x over previous
#include <cuda_runtime.h>
#include <cuda_bf16.h>
#include <cstdint>
#include <math.h>

#define D_MODEL 1024
#define NHEAD 16
#define DKH 64
#define BATCH 4
#define SEQ 2048
#define MTOK (BATCH * SEQ)   // 8192

// 0.125 * log2(e): folded into Q so attention scores are exp2-ready
#define QSCALE 0.18033688011112042f

// ---------------------------------------------------------------------------
// Scratch (alloc-free rule: __device__ globals)
// ---------------------------------------------------------------------------
__device__ __nv_bfloat16 g_xh[MTOK * D_MODEL];
__device__ __nv_bfloat16 g_xl[MTOK * D_MODEL];
__device__ __nv_bfloat16 g_qh[MTOK * D_MODEL];   // [B,H,S,64] (pre-scaled)
__device__ __nv_bfloat16 g_ql[MTOK * D_MODEL];
__device__ __nv_bfloat16 g_kh[MTOK * D_MODEL];
__device__ __nv_bfloat16 g_kl[MTOK * D_MODEL];
__device__ __nv_bfloat16 g_vh[MTOK * D_MODEL];
__device__ __nv_bfloat16 g_vl[MTOK * D_MODEL];
__device__ __nv_bfloat16 g_ah[MTOK * D_MODEL];   // attn out [B,S,D]
__device__ __nv_bfloat16 g_al[MTOK * D_MODEL];
__device__ __nv_bfloat16 g_wqh[D_MODEL * D_MODEL];
__device__ __nv_bfloat16 g_wql[D_MODEL * D_MODEL];
__device__ __nv_bfloat16 g_wkh[D_MODEL * D_MODEL];
__device__ __nv_bfloat16 g_wkl[D_MODEL * D_MODEL];
__device__ __nv_bfloat16 g_wvh[D_MODEL * D_MODEL];
__device__ __nv_bfloat16 g_wvl[D_MODEL * D_MODEL];
__device__ __nv_bfloat16 g_woh[D_MODEL * D_MODEL];
__device__ __nv_bfloat16 g_wol[D_MODEL * D_MODEL];

// ---------------------------------------------------------------------------
// helpers (arch-portable only: cp.async / ldmatrix / mma.sync)
// ---------------------------------------------------------------------------
__device__ __forceinline__ uint32_t smem_u32(const void* p) {
    uint32_t a;
    asm("{ .reg .u64 t; cvta.to.shared.u64 t, %1; cvt.u32.u64 %0, t; }"
        : "=r"(a) : "l"(p));
    return a;
}

#define LDMATRIX_X4(r0, r1, r2, r3, addr) \
    asm volatile("ldmatrix.sync.aligned.m8n8.x4.shared.b16 {%0,%1,%2,%3}, [%4];" \
        : "=r"(r0), "=r"(r1), "=r"(r2), "=r"(r3) : "r"(addr))

#define LDMATRIX_X4_T(r0, r1, r2, r3, addr) \
    asm volatile("ldmatrix.sync.aligned.m8n8.x4.trans.shared.b16 {%0,%1,%2,%3}, [%4];" \
        : "=r"(r0), "=r"(r1), "=r"(r2), "=r"(r3) : "r"(addr))

#define MMA16816(d, a0, a1, a2, a3, b0, b1) \
    asm volatile("mma.sync.aligned.m16n8k16.row.col.f32.bf16.bf16.f32 " \
        "{%0,%1,%2,%3}, {%4,%5,%6,%7}, {%8,%9}, {%0,%1,%2,%3};" \
        : "+f"((d)[0]), "+f"((d)[1]), "+f"((d)[2]), "+f"((d)[3]) \
        : "r"(a0), "r"(a1), "r"(a2), "r"(a3), "r"(b0), "r"(b1))

#define CP_ASYNC16(saddr, gaddr) \
    asm volatile("cp.async.cg.shared.global [%0], [%1], 16;" \
        :: "r"(saddr), "l"(gaddr))
#define CP_COMMIT() asm volatile("cp.async.commit_group;" ::: "memory")
#define CP_WAIT(n)  asm volatile("cp.async.wait_group %0;" :: "n"(n) : "memory")

#define PACK_BF16X2(r, lo, hi) \
    asm("cvt.rn.bf16x2.f32 %0, %1, %2;" : "=r"(r) : "f"(hi), "f"(lo))

__device__ __forceinline__ void split2(float v0, float v1,
                                       uint32_t& ph, uint32_t& pl) {
    PACK_BF16X2(ph, v0, v1);
    const float f0 = __uint_as_float(ph << 16);
    const float f1 = __uint_as_float(ph & 0xffff0000u);
    PACK_BF16X2(pl, v0 - f0, v1 - f1);
}

__device__ __forceinline__ float ex2(float x) {
    float y;
    asm("ex2.approx.f32 %0, %1;" : "=f"(y) : "f"(x));
    return y;
}

// ---------------------------------------------------------------------------
// fused fp32 -> bf16 hi/lo split: x (2M float4) + 4 weights (256K float4 each)
// ---------------------------------------------------------------------------
#define NX4 (MTOK * D_MODEL / 4)       // 2097152
#define NW4 (D_MODEL * D_MODEL / 4)    // 262144
#define NSPLIT4 (NX4 + 4 * NW4)        // 3145728

__global__ void __launch_bounds__(256) split_all_kernel(
    const float* __restrict__ x,
    const float* __restrict__ w0, const float* __restrict__ w1,
    const float* __restrict__ w2, const float* __restrict__ w3,
    __nv_bfloat16* __restrict__ xh, __nv_bfloat16* __restrict__ xl,
    __nv_bfloat16* __restrict__ h0, __nv_bfloat16* __restrict__ l0,
    __nv_bfloat16* __restrict__ h1, __nv_bfloat16* __restrict__ l1,
    __nv_bfloat16* __restrict__ h2, __nv_bfloat16* __restrict__ l2,
    __nv_bfloat16* __restrict__ h3, __nv_bfloat16* __restrict__ l3)
{
    const int id = blockIdx.x * 256 + threadIdx.x;
    if (id >= NSPLIT4) return;
    const float* in;
    __nv_bfloat16 *hi, *lo;
    int i;
    if (id < NX4) {
        in = x; hi = xh; lo = xl; i = id;
    } else {
        const int r = id - NX4;
        const int which = r / NW4;
        i = r - which * NW4;
        in = (which == 0) ? w0 : (which == 1) ? w1 : (which == 2) ? w2 : w3;
        hi = (which == 0) ? h0 : (which == 1) ? h1 : (which == 2) ? h2 : h3;
        lo = (which == 0) ? l0 : (which == 1) ? l1 : (which == 2) ? l2 : l3;
    }
    float4 v = ((const float4*)in)[i];
    uint32_t h01, l01, h23, l23;
    split2(v.x, v.y, h01, l01);
    split2(v.z, v.w, h23, l23);
    ((uint32_t*)hi)[2 * i]     = h01;
    ((uint32_t*)hi)[2 * i + 1] = h23;
    ((uint32_t*)lo)[2 * i]     = l01;
    ((uint32_t*)lo)[2 * i + 1] = l23;
}

// ---------------------------------------------------------------------------
// mma.sync bf16 3-pass GEMM body. 128x128 tile/CTA, BK=32, XOR swizzle,
// 3-stage, 2 CTAs/SM. SINGLE barrier per chunk: wait -> sync -> prefetch
// (c+2 into the buffer freed at c-1, proven by the barrier) -> compute.
// ---------------------------------------------------------------------------
#define BM 128
#define BN 128
#define BK 32
#define CHUNKS (D_MODEL / BK)          // 32
#define TILE_B (128 * 64)              // 8192 bytes, swizzled
#define STAGE_B (4 * TILE_B)           // 32768 (Ah,Al,Bh,Bl)
#define GEMM_SMEM (3 * STAGE_B)        // 98304

template <int MODE>
__device__ __forceinline__ void gemm_body(
    const __nv_bfloat16* __restrict__ Ah, const __nv_bfloat16* __restrict__ Al,
    const __nv_bfloat16* __restrict__ Bh, const __nv_bfloat16* __restrict__ Bl,
    __nv_bfloat16* __restrict__ Ch, __nv_bfloat16* __restrict__ Cl,
    float* __restrict__ Cf, const int bm, const int bn, const float cscale)
{
    extern __shared__ __align__(128) char smem[];
    const uint32_t sbase = smem_u32(smem);
    const int tid  = threadIdx.x;
    const int wid  = tid >> 5;
    const int lane = tid & 31;
    const int K = D_MODEL;

    const int warp_m = wid >> 2;
    const int warp_n = wid & 3;

    auto load_stage = [&](int chunk, int s) {
        const uint32_t st = sbase + s * STAGE_B;
        const int k0 = chunk * BK;
#pragma unroll
        for (int u = 0; u < 8; u++) {
            const int id = u * 256 + tid;
            const int t = id >> 9;
            const int idx = id & 511;
            const int row = idx >> 2;
            const int c = idx & 3;
            const __nv_bfloat16* g;
            int grow;
            if (t == 0)      { g = Ah; grow = bm + row; }
            else if (t == 1) { g = Al; grow = bm + row; }
            else if (t == 2) { g = Bh; grow = bn + row; }
            else             { g = Bl; grow = bn + row; }
            const __nv_bfloat16* gaddr = g + (size_t)grow * K + k0 + c * 8;
            const uint32_t saddr = st + t * TILE_B + row * 64 +
                                   (((uint32_t)(c ^ ((row >> 1) & 3))) << 4);
            CP_ASYNC16(saddr, gaddr);
        }
        CP_COMMIT();
    };

    load_stage(0, 0);
    load_stage(1, 1);

    float acc[4][4][4];
#pragma unroll
    for (int i = 0; i < 4; i++)
#pragma unroll
        for (int j = 0; j < 4; j++)
#pragma unroll
            for (int r = 0; r < 4; r++) acc[i][j][r] = 0.0f;

    const int a_row = warp_m * 64 + (lane & 15);
    const uint32_t a_off = (uint32_t)a_row * 64 +
        ((uint32_t)(((lane >> 4) ^ ((a_row >> 1) & 3))) << 4);
    const int b_row = warp_n * 32 + ((lane >> 4) & 1) * 8 + (lane & 7);
    const uint32_t b_off = (uint32_t)b_row * 64 +
        ((uint32_t)((((lane >> 3) & 1) ^ ((b_row >> 1) & 3))) << 4);

    int s = 0;
    int s2 = 2;   // buffer for chunk+2
    for (int chunk = 0; chunk < CHUNKS; chunk++) {
        if (chunk < CHUNKS - 1) CP_WAIT(1);
        else                    CP_WAIT(0);
        __syncthreads();
        if (chunk + 2 < CHUNKS) load_stage(chunk + 2, s2);
        const uint32_t st = sbase + s * STAGE_B;
        const uint32_t aH = st + a_off;
        const uint32_t aL = st + TILE_B + a_off;
        const uint32_t bH = st + 2 * TILE_B + b_off;
        const uint32_t bL = st + 3 * TILE_B + b_off;

#pragma unroll
        for (int ks = 0; ks < 2; ks++) {
            const uint32_t kx = (uint32_t)ks << 5;
            uint32_t fAH[4][4], fAL[4][4], fBH[4][2], fBL[4][2];
#pragma unroll
            for (int mt = 0; mt < 4; mt++) {
                LDMATRIX_X4(fAH[mt][0], fAH[mt][1], fAH[mt][2], fAH[mt][3],
                            (aH + mt * 1024) ^ kx);
                LDMATRIX_X4(fAL[mt][0], fAL[mt][1], fAL[mt][2], fAL[mt][3],
                            (aL + mt * 1024) ^ kx);
            }
#pragma unroll
            for (int np = 0; np < 2; np++) {
                LDMATRIX_X4(fBH[2 * np][0], fBH[2 * np][1],
                            fBH[2 * np + 1][0], fBH[2 * np + 1][1],
                            (bH + np * 1024) ^ kx);
                LDMATRIX_X4(fBL[2 * np][0], fBL[2 * np][1],
                            fBL[2 * np + 1][0], fBL[2 * np + 1][1],
                            (bL + np * 1024) ^ kx);
            }
#pragma unroll
            for (int mt = 0; mt < 4; mt++)
#pragma unroll
                for (int nt = 0; nt < 4; nt++) {
                    MMA16816(acc[mt][nt], fAH[mt][0], fAH[mt][1], fAH[mt][2],
                             fAH[mt][3], fBH[nt][0], fBH[nt][1]);
                    MMA16816(acc[mt][nt], fAH[mt][0], fAH[mt][1], fAH[mt][2],
                             fAH[mt][3], fBL[nt][0], fBL[nt][1]);
                    MMA16816(acc[mt][nt], fAL[mt][0], fAL[mt][1], fAL[mt][2],
                             fAL[mt][3], fBH[nt][0], fBH[nt][1]);
                }
        }
        s  = (s == 2)  ? 0 : s + 1;
        s2 = (s2 == 2) ? 0 : s2 + 1;
    }
    __syncthreads();   // protect nothing-after; keeps epilogue store ordering

#pragma unroll
    for (int mt = 0; mt < 4; mt++) {
#pragma unroll
        for (int half = 0; half < 2; half++) {
            const int m = bm + warp_m * 64 + mt * 16 + (lane >> 2) + half * 8;
#pragma unroll
            for (int nt = 0; nt < 4; nt++) {
                const int n = bn + warp_n * 32 + nt * 8 + (lane & 3) * 2;
                const float v0 = acc[mt][nt][2 * half] * cscale;
                const float v1 = acc[mt][nt][2 * half + 1] * cscale;
                if (MODE == 0) {
                    const int b = m >> 11;
                    const int sq = m & 2047;
                    const int h = n >> 6;
                    const int dd = n & 63;
                    const size_t idx =
                        ((size_t)((b * NHEAD + h) * SEQ + sq) << 6) + dd;
                    uint32_t ph, pl;
                    split2(v0, v1, ph, pl);
                    *(uint32_t*)&Ch[idx] = ph;
                    *(uint32_t*)&Cl[idx] = pl;
                } else {
                    const size_t idx = (size_t)m * D_MODEL + n;
                    *(float2*)&Cf[idx] = make_float2(v0, v1);
                }
            }
        }
    }
}

__global__ void __launch_bounds__(256, 2) gemm_qkv_kernel(
    const __nv_bfloat16* __restrict__ xh, const __nv_bfloat16* __restrict__ xl,
    const __nv_bfloat16* __restrict__ wqh, const __nv_bfloat16* __restrict__ wql,
    const __nv_bfloat16* __restrict__ wkh, const __nv_bfloat16* __restrict__ wkl,
    const __nv_bfloat16* __restrict__ wvh, const __nv_bfloat16* __restrict__ wvl,
    __nv_bfloat16* __restrict__ qh, __nv_bfloat16* __restrict__ ql,
    __nv_bfloat16* __restrict__ kh, __nv_bfloat16* __restrict__ kl,
    __nv_bfloat16* __restrict__ vh, __nv_bfloat16* __restrict__ vl)
{
    const int proj = blockIdx.x >> 3;
    const int bn = (blockIdx.x & 7) * BN;
    const int bm = blockIdx.y * BM;
    const __nv_bfloat16* Bh = (proj == 0) ? wqh : (proj == 1) ? wkh : wvh;
    const __nv_bfloat16* Bl = (proj == 0) ? wql : (proj == 1) ? wkl : wvl;
    __nv_bfloat16* Ch = (proj == 0) ? qh : (proj == 1) ? kh : vh;
    __nv_bfloat16* Cl = (proj == 0) ? ql : (proj == 1) ? kl : vl;
    const float cs = (proj == 0) ? QSCALE : 1.0f;   // fold 1/8*log2e into Q
    gemm_body<0>(xh, xl, Bh, Bl, Ch, Cl, nullptr, bm, bn, cs);
}

__global__ void __launch_bounds__(256, 2) gemm_out_kernel(
    const __nv_bfloat16* __restrict__ ah, const __nv_bfloat16* __restrict__ al,
    const __nv_bfloat16* __restrict__ woh, const __nv_bfloat16* __restrict__ wol,
    float* __restrict__ out)
{
    gemm_body<1>(ah, al, woh, wol, nullptr, nullptr, out,
                 blockIdx.y * BM, blockIdx.x * BN, 1.0f);
}

// ---------------------------------------------------------------------------
// Tensor-core causal flash attention (bf16 3-pass, fp32 accum).
// SINGLE barrier per KV tile: wait(0) -> sync -> prefetch(jt+1 into the
// buffer freed at jt-1, proven by the barrier) -> compute. Warps can drift
// across the softmax phase (desync without extra registers).
// ---------------------------------------------------------------------------
#define ATPAD 72
#define AT_STRIDE (ATPAD * 2)          // 144 bytes/row
#define AT_TILE_B (64 * AT_STRIDE)     // 9216
#define AT_STAGE_B (4 * AT_TILE_B)     // 36864 (Kh,Kl,Vh,Vl)
#define ATTN_SMEM (2 * AT_STAGE_B)     // 73728

__global__ void __launch_bounds__(128, 3) attn_mma_kernel(
    const __nv_bfloat16* __restrict__ Qh, const __nv_bfloat16* __restrict__ Ql,
    const __nv_bfloat16* __restrict__ Kh, const __nv_bfloat16* __restrict__ Kl,
    const __nv_bfloat16* __restrict__ Vh, const __nv_bfloat16* __restrict__ Vl,
    __nv_bfloat16* __restrict__ Ah, __nv_bfloat16* __restrict__ Al)
{
    extern __shared__ __align__(128) char smem[];
    const uint32_t sbase = smem_u32(smem);
    const int tid  = threadIdx.x;
    const int wid  = tid >> 5;
    const int lane = tid & 31;
    const int bh = blockIdx.y;
    const int qb = (int)gridDim.x - 1 - (int)blockIdx.x;   // heavy CTAs first
    const int q0 = qb * 64;
    const size_t base_off = (size_t)bh * SEQ * DKH;

#pragma unroll
    for (int u = 0; u < 8; u++) {
        const int id = u * 128 + tid;
        const int t = id >> 9;
        const int idx = id & 511;
        const int row = idx >> 3;
        const int c = idx & 7;
        const __nv_bfloat16* g = t ? Ql : Qh;
        CP_ASYNC16(sbase + t * AT_TILE_B + row * AT_STRIDE + c * 16,
                   g + base_off + (size_t)(q0 + row) * DKH + c * 8);
    }
    CP_COMMIT();
    CP_WAIT(0);
    __syncthreads();

    uint32_t Qh_[4][4], Ql_[4][4];
    {
        const uint32_t qa =
            sbase + (16 * wid + (lane & 15)) * AT_STRIDE + (lane >> 4) * 16;
#pragma unroll
        for (int ks = 0; ks < 4; ks++) {
            LDMATRIX_X4(Qh_[ks][0], Qh_[ks][1], Qh_[ks][2], Qh_[ks][3],
                        qa + ks * 32);
            LDMATRIX_X4(Ql_[ks][0], Ql_[ks][1], Ql_[ks][2], Ql_[ks][3],
                        qa + AT_TILE_B + ks * 32);
        }
    }
    __syncthreads();   // Q consumed; smem reusable

    auto load_kv = [&](int jt, int buf) {
        const uint32_t st = sbase + buf * AT_STAGE_B;
        const int k0 = jt * 64;
#pragma unroll
        for (int u = 0; u < 16; u++) {
            const int id = u * 128 + tid;
            const int t = id >> 9;
            const int idx = id & 511;
            const int row = idx >> 3;
            const int c = idx & 7;
            const __nv_bfloat16* g = (t == 0) ? Kh : (t == 1) ? Kl
                                     : (t == 2) ? Vh : Vl;
            CP_ASYNC16(st + t * AT_TILE_B + row * AT_STRIDE + c * 16,
                       g + base_off + (size_t)(k0 + row) * DKH + c * 8);
        }
        CP_COMMIT();
    };

    float O_[8][4];
#pragma unroll
    for (int i = 0; i < 8; i++)
#pragma unroll
        for (int j = 0; j < 4; j++) O_[i][j] = 0.0f;
    float m_lo = -1e30f, m_hi = -1e30f;
    float l_lo = 0.0f, l_hi = 0.0f;     // per-lane partial sums (deferred red.)

    const int row_lo = q0 + 16 * wid + (lane >> 2);
    const int row_hi = row_lo + 8;
    const uint32_t b_off =
        (((lane >> 4) & 1) * 8 + (lane & 7)) * AT_STRIDE + ((lane >> 3) & 1) * 16;
    const uint32_t v_off = (lane & 15) * AT_STRIDE + (lane >> 4) * 16;

    const int jmax = qb;
    load_kv(0, 0);

    for (int jt = 0; jt <= jmax; jt++) {
        CP_WAIT(0);
        __syncthreads();
        if (jt < jmax) load_kv(jt + 1, (jt + 1) & 1);
        const uint32_t st = sbase + (jt & 1) * AT_STAGE_B;

        float S_[8][4];
#pragma unroll
        for (int i = 0; i < 8; i++)
#pragma unroll
            for (int j = 0; j < 4; j++) S_[i][j] = 0.0f;

#pragma unroll
        for (int ks = 0; ks < 4; ks++)
#pragma unroll
            for (int np = 0; np < 4; np++) {
                uint32_t f0, f1, f2, f3, g0, g1, g2, g3;
                const uint32_t ka = st + np * 16 * AT_STRIDE + b_off + ks * 32;
                LDMATRIX_X4(f0, f1, f2, f3, ka);
                LDMATRIX_X4(g0, g1, g2, g3, ka + AT_TILE_B);
                MMA16816(S_[2 * np], Qh_[ks][0], Qh_[ks][1], Qh_[ks][2],
                         Qh_[ks][3], f0, f1);
                MMA16816(S_[2 * np + 1], Qh_[ks][0], Qh_[ks][1], Qh_[ks][2],
                         Qh_[ks][3], f2, f3);
                MMA16816(S_[2 * np], Qh_[ks][0], Qh_[ks][1], Qh_[ks][2],
                         Qh_[ks][3], g0, g1);
                MMA16816(S_[2 * np + 1], Qh_[ks][0], Qh_[ks][1], Qh_[ks][2],
                         Qh_[ks][3], g2, g3);
                MMA16816(S_[2 * np], Ql_[ks][0], Ql_[ks][1], Ql_[ks][2],
                         Ql_[ks][3], f0, f1);
                MMA16816(S_[2 * np + 1], Ql_[ks][0], Ql_[ks][1], Ql_[ks][2],
                         Ql_[ks][3], f2, f3);
            }

        if (jt == jmax) {
            const int k0g = jt * 64;
#pragma unroll
            for (int nt = 0; nt < 8; nt++) {
                const int col = k0g + 8 * nt + 2 * (lane & 3);
                if (col     > row_lo) S_[nt][0] = -1e30f;
                if (col + 1 > row_lo) S_[nt][1] = -1e30f;
                if (col     > row_hi) S_[nt][2] = -1e30f;
                if (col + 1 > row_hi) S_[nt][3] = -1e30f;
            }
        }

        float rmax_lo = -1e30f, rmax_hi = -1e30f;
#pragma unroll
        for (int nt = 0; nt < 8; nt++) {
            rmax_lo = fmaxf(rmax_lo, fmaxf(S_[nt][0], S_[nt][1]));
            rmax_hi = fmaxf(rmax_hi, fmaxf(S_[nt][2], S_[nt][3]));
        }
        rmax_lo = fmaxf(rmax_lo, __shfl_xor_sync(0xffffffffu, rmax_lo, 1));
        rmax_lo = fmaxf(rmax_lo, __shfl_xor_sync(0xffffffffu, rmax_lo, 2));
        rmax_hi = fmaxf(rmax_hi, __shfl_xor_sync(0xffffffffu, rmax_hi, 1));
        rmax_hi = fmaxf(rmax_hi, __shfl_xor_sync(0xffffffffu, rmax_hi, 2));

        const float mn_lo = fmaxf(m_lo, rmax_lo);
        const float mn_hi = fmaxf(m_hi, rmax_hi);
        const float al_lo = ex2(m_lo - mn_lo);
        const float al_hi = ex2(m_hi - mn_hi);
        m_lo = mn_lo; m_hi = mn_hi;

        float rs_lo = 0.0f, rs_hi = 0.0f;
#pragma unroll
        for (int nt = 0; nt < 8; nt++) {
            S_[nt][0] = ex2(S_[nt][0] - m_lo);
            S_[nt][1] = ex2(S_[nt][1] - m_lo);
            S_[nt][2] = ex2(S_[nt][2] - m_hi);
            S_[nt][3] = ex2(S_[nt][3] - m_hi);
            rs_lo += S_[nt][0] + S_[nt][1];
            rs_hi += S_[nt][2] + S_[nt][3];
        }
        l_lo = l_lo * al_lo + rs_lo;
        l_hi = l_hi * al_hi + rs_hi;

#pragma unroll
        for (int nt = 0; nt < 8; nt++) {
            O_[nt][0] *= al_lo; O_[nt][1] *= al_lo;
            O_[nt][2] *= al_hi; O_[nt][3] *= al_hi;
        }

#pragma unroll
        for (int kp = 0; kp < 4; kp++) {
            uint32_t Ph[4], Pl[4];
            split2(S_[2 * kp][0],     S_[2 * kp][1],     Ph[0], Pl[0]);
            split2(S_[2 * kp][2],     S_[2 * kp][3],     Ph[1], Pl[1]);
            split2(S_[2 * kp + 1][0], S_[2 * kp + 1][1], Ph[2], Pl[2]);
            split2(S_[2 * kp + 1][2], S_[2 * kp + 1][3], Ph[3], Pl[3]);
#pragma unroll
            for (int dp = 0; dp < 4; dp++) {
                uint32_t v0, v1, v2, v3, w0, w1, w2, w3;
                const uint32_t va = st + 2 * AT_TILE_B +
                                    kp * 16 * AT_STRIDE + v_off + dp * 32;
                LDMATRIX_X4_T(v0, v1, v2, v3, va);
                LDMATRIX_X4_T(w0, w1, w2, w3, va + AT_TILE_B);
                MMA16816(O_[2 * dp], Ph[0], Ph[1], Ph[2], Ph[3], v0, v1);
                MMA16816(O_[2 * dp + 1], Ph[0], Ph[1], Ph[2], Ph[3], v2, v3);
                MMA16816(O_[2 * dp], Ph[0], Ph[1], Ph[2], Ph[3], w0, w1);
                MMA16816(O_[2 * dp + 1], Ph[0], Ph[1], Ph[2], Ph[3], w2, w3);
                MMA16816(O_[2 * dp], Pl[0], Pl[1], Pl[2], Pl[3], v0, v1);
                MMA16816(O_[2 * dp + 1], Pl[0], Pl[1], Pl[2], Pl[3], v2, v3);
            }
        }
        // no trailing barrier: next iteration's sync precedes buffer reuse
    }

    l_lo += __shfl_xor_sync(0xffffffffu, l_lo, 1);
    l_lo += __shfl_xor_sync(0xffffffffu, l_lo, 2);
    l_hi += __shfl_xor_sync(0xffffffffu, l_hi, 1);
    l_hi += __shfl_xor_sync(0xffffffffu, l_hi, 2);
    const float inv_lo = 1.0f / l_lo;
    const float inv_hi = 1.0f / l_hi;
    const int b = bh >> 4;
    const int hh = bh & 15;
#pragma unroll
    for (int nt = 0; nt < 8; nt++) {
        const int col = hh * DKH + 8 * nt + 2 * (lane & 3);
        uint32_t ph, pl;
        split2(O_[nt][0] * inv_lo, O_[nt][1] * inv_lo, ph, pl);
        const size_t i0 = (size_t)(b * SEQ + row_lo) * D_MODEL + col;
        *(uint32_t*)&Ah[i0] = ph;
        *(uint32_t*)&Al[i0] = pl;
        split2(O_[nt][2] * inv_hi, O_[nt][3] * inv_hi, ph, pl);
        const size_t i1 = (size_t)(b * SEQ + row_hi) * D_MODEL + col;
        *(uint32_t*)&Ah[i1] = ph;
        *(uint32_t*)&Al[i1] = pl;
    }
}

// ---------------------------------------------------------------------------
// launch
// ---------------------------------------------------------------------------
extern "C" void kernel_launch(void* const* d_in, const int* in_sizes, int n_in,
                              void* d_out, int out_size)
{
    (void)in_sizes; (void)n_in; (void)out_size;
    const float* x  = (const float*)d_in[0];
    const float* wq = (const float*)d_in[1];
    const float* wk = (const float*)d_in[2];
    const float* wv = (const float*)d_in[3];
    const float* wo = (const float*)d_in[4];
    float* out = (float*)d_out;

    __nv_bfloat16 *xh, *xl, *qh, *ql, *kh, *kl, *vh, *vl, *ah, *al;
    __nv_bfloat16 *wqh, *wql, *wkh, *wkl, *wvh, *wvl, *woh, *wol;
    cudaGetSymbolAddress((void**)&xh, g_xh);
    cudaGetSymbolAddress((void**)&xl, g_xl);
    cudaGetSymbolAddress((void**)&qh, g_qh);
    cudaGetSymbolAddress((void**)&ql, g_ql);
    cudaGetSymbolAddress((void**)&kh, g_kh);
    cudaGetSymbolAddress((void**)&kl, g_kl);
    cudaGetSymbolAddress((void**)&vh, g_vh);
    cudaGetSymbolAddress((void**)&vl, g_vl);
    cudaGetSymbolAddress((void**)&ah, g_ah);
    cudaGetSymbolAddress((void**)&al, g_al);
    cudaGetSymbolAddress((void**)&wqh, g_wqh);
    cudaGetSymbolAddress((void**)&wql, g_wql);
    cudaGetSymbolAddress((void**)&wkh, g_wkh);
    cudaGetSymbolAddress((void**)&wkl, g_wkl);
    cudaGetSymbolAddress((void**)&wvh, g_wvh);
    cudaGetSymbolAddress((void**)&wvl, g_wvl);
    cudaGetSymbolAddress((void**)&woh, g_woh);
    cudaGetSymbolAddress((void**)&wol, g_wol);

    cudaFuncSetAttribute(gemm_qkv_kernel,
                         cudaFuncAttributeMaxDynamicSharedMemorySize, GEMM_SMEM);
    cudaFuncSetAttribute(gemm_out_kernel,
                         cudaFuncAttributeMaxDynamicSharedMemorySize, GEMM_SMEM);
    cudaFuncSetAttribute(attn_mma_kernel,
                         cudaFuncAttributeMaxDynamicSharedMemorySize, ATTN_SMEM);

    split_all_kernel<<<(NSPLIT4 + 255) / 256, 256>>>(
        x, wq, wk, wv, wo, xh, xl,
        wqh, wql, wkh, wkl, wvh, wvl, woh, wol);

    gemm_qkv_kernel<<<dim3(24, MTOK / BM), 256, GEMM_SMEM>>>(
        xh, xl, wqh, wql, wkh, wkl, wvh, wvl, qh, ql, kh, kl, vh, vl);

    attn_mma_kernel<<<dim3(SEQ / 64, BATCH * NHEAD), 128, ATTN_SMEM>>>(
        qh, ql, kh, kl, vh, vl, ah, al);

    gemm_out_kernel<<<dim3(D_MODEL / BN, MTOK / BM), 256, GEMM_SMEM>>>(
        ah, al, woh, wol, out);
}